// round 6
// baseline (speedup 1.0000x reference)
#include <cuda_runtime.h>
#include <cuda_fp16.h>
#include <cstdint>

#define BATCH   16
#define NNODES  10000
#define HDIM    128
#define NEDGES  320000
#define NROWS   (BATCH * NNODES)      // 160000
#define NTILES  (NROWS / 128)         // 1250

// ---------------- scratch (device globals; no allocation allowed) ----------
__device__ int    g_counts[NNODES];
__device__ int    g_offsets[NNODES + 1];
__device__ int    g_cursor[NNODES];
__device__ int    g_csr[NEDGES];
__device__ __half g_emb16[(size_t)NROWS * HDIM];   // 41 MB fp16 copy
__device__ __half g_w1_16[256 * 128];
__device__ __half g_w2_16[128 * 128];

// ---------------- helpers -----------------------------------------------------
__device__ __forceinline__ uint32_t smem_u32(const void* p) {
    uint32_t a;
    asm("{ .reg .u64 t; cvta.to.shared.u64 t, %1; cvt.u32.u64 %0, t; }"
        : "=r"(a) : "l"(p));
    return a;
}
__device__ __forceinline__ void ldsm4(uint32_t* r, uint32_t a) {
    asm volatile("ldmatrix.sync.aligned.m8n8.x4.shared.b16 {%0,%1,%2,%3}, [%4];"
                 : "=r"(r[0]), "=r"(r[1]), "=r"(r[2]), "=r"(r[3]) : "r"(a));
}
__device__ __forceinline__ void ldsm4t(uint32_t* r, uint32_t a) {
    asm volatile("ldmatrix.sync.aligned.m8n8.x4.trans.shared.b16 {%0,%1,%2,%3}, [%4];"
                 : "=r"(r[0]), "=r"(r[1]), "=r"(r[2]), "=r"(r[3]) : "r"(a));
}
__device__ __forceinline__ void mma16816(float* c, const uint32_t* a,
                                         uint32_t b0, uint32_t b1) {
    asm volatile(
        "mma.sync.aligned.m16n8k16.row.col.f32.f16.f16.f32 "
        "{%0,%1,%2,%3}, {%4,%5,%6,%7}, {%8,%9}, {%0,%1,%2,%3};"
        : "+f"(c[0]), "+f"(c[1]), "+f"(c[2]), "+f"(c[3])
        : "r"(a[0]), "r"(a[1]), "r"(a[2]), "r"(a[3]), "r"(b0), "r"(b1));
}
__device__ __forceinline__ void bar_consumers() {
    asm volatile("bar.sync 1, 256;" ::: "memory");
}

// ---------------- CSR build ----------------------------------------------------
__global__ void hist_k(const int* __restrict__ edge) {
    int e = blockIdx.x * blockDim.x + threadIdx.x;
    if (e < NEDGES) atomicAdd(&g_counts[edge[NEDGES + e]], 1);
}
__global__ void scan_k() {
    __shared__ int part[1024];
    const int CH = 10;
    int t = threadIdx.x;
    int local[CH];
    int s = 0;
#pragma unroll
    for (int i = 0; i < CH; i++) {
        int idx = t * CH + i;
        int v = (idx < NNODES) ? g_counts[idx] : 0;
        local[i] = s;
        s += v;
    }
    part[t] = s;
    __syncthreads();
    for (int off = 1; off < 1024; off <<= 1) {
        int v = (t >= off) ? part[t - off] : 0;
        __syncthreads();
        part[t] += v;
        __syncthreads();
    }
    int excl = (t == 0) ? 0 : part[t - 1];
#pragma unroll
    for (int i = 0; i < CH; i++) {
        int idx = t * CH + i;
        if (idx < NNODES) {
            int o = excl + local[i];
            g_offsets[idx] = o;
            g_cursor[idx]  = o;
        }
    }
    if (t == 1023) g_offsets[NNODES] = part[1023];
}
__global__ void scatter_k(const int* __restrict__ edge) {
    int e = blockIdx.x * blockDim.x + threadIdx.x;
    if (e < NEDGES) {
        int d = edge[NEDGES + e];
        int p = atomicAdd(&g_cursor[d], 1);
        g_csr[p] = edge[e];
    }
}

// ---------------- emb fp32 -> fp16 copy (+ counts zeroing folded in) ----------
__global__ __launch_bounds__(256)
void econv16_k(const float* __restrict__ emb) {
    size_t gid = (size_t)blockIdx.x * 256 + threadIdx.x;
    if (gid < NNODES) g_counts[gid] = 0;
    const float4* s = (const float4*)(emb) + gid * 2;
    float4 a = s[0], b = s[1];
    __half2 h0 = __float22half2_rn(make_float2(a.x, a.y));
    __half2 h1 = __float22half2_rn(make_float2(a.z, a.w));
    __half2 h2 = __float22half2_rn(make_float2(b.x, b.y));
    __half2 h3 = __float22half2_rn(make_float2(b.z, b.w));
    uint4 o;
    o.x = *(uint32_t*)&h0; o.y = *(uint32_t*)&h1;
    o.z = *(uint32_t*)&h2; o.w = *(uint32_t*)&h3;
    *((uint4*)g_emb16 + gid) = o;
}

// ---------------- weight fp32 -> fp16 ------------------------------------------
__global__ void wconv_k(const float* __restrict__ W, __half* o16, int total) {
    int i = blockIdx.x * blockDim.x + threadIdx.x;
    if (i < total) o16[i] = __float2half_rn(W[i]);
}

// ---------------- fused gather + GEMM1 + GEMM2, warp-specialized ---------------
// 448 threads: warps 0-7 consumers (MMA), warps 8-13 producers (gather+copy).
// smem 224KB:
//   [0, 64K)     W1 fp16 swizzled (loaded once)
//   [64K, 96K)   W2 fp16 swizzled (loaded once)
//   [96K, 160K)  ctx buf0: 4 chunks x 16KB ([nbr0|nbr1|emb0|emb1]); h -> chunks 0-1
//   [160K,224K)  ctx buf1
#define SM_W1   0
#define SM_W2   65536
#define SM_BUF  98304
#define SMEM_FUSED 229376

// producer: build full ctx tile (gather -> chunks 0-1, emb copy -> chunks 2-3)
__device__ __forceinline__ void produce(char* buf, int rowBase, int ptid,
                                        int lane, int pw) {
    // emb copy -> chunks 2,3 (pure 16B moves)
    for (int idx = ptid; idx < 2048; idx += 192) {
        int r = idx >> 4, c = idx & 15;
        uint32_t off = (uint32_t)(r * 128 + (((c & 7) ^ (r & 7)) << 4));
        *(uint4*)(buf + (2 + (c >> 3)) * 16384 + off) =
            *(const uint4*)(g_emb16 + (size_t)(rowBase + r) * 128 + c * 8);
    }
    // gather -> chunks 0,1 ; lane covers cols 4L..4L+3
    int chunk = lane >> 4;
    uint32_t c16  = (uint32_t)((lane & 15) >> 1);
    uint32_t h8   = (uint32_t)((lane & 1) * 8);
    for (int local = pw; local < 128; local += 6) {
        int row = rowBase + local;
        int b = row / NNODES;
        int n = row - b * NNODES;
        const __half* embB = g_emb16 + ((size_t)b * NNODES) * 128 + lane * 4;
        int beg = g_offsets[n], end = g_offsets[n + 1];
        float4 acc = make_float4(0.f, 0.f, 0.f, 0.f);
        int i = beg;
        for (; i + 8 <= end; i += 8) {
            uint2 p[8];
#pragma unroll
            for (int q = 0; q < 8; q++)
                p[q] = *(const uint2*)(embB + (size_t)__ldg(g_csr + i + q) * 128);
#pragma unroll
            for (int q = 0; q < 8; q++) {
                float2 f0 = __half22float2(*(__half2*)&p[q].x);
                float2 f1 = __half22float2(*(__half2*)&p[q].y);
                acc.x += f0.x; acc.y += f0.y; acc.z += f1.x; acc.w += f1.y;
            }
        }
        for (; i < end; i++) {
            uint2 p = *(const uint2*)(embB + (size_t)__ldg(g_csr + i) * 128);
            float2 f0 = __half22float2(*(__half2*)&p.x);
            float2 f1 = __half22float2(*(__half2*)&p.y);
            acc.x += f0.x; acc.y += f0.y; acc.z += f1.x; acc.w += f1.y;
        }
        __half2 h0 = __floats2half2_rn(acc.x, acc.y);
        __half2 h1 = __floats2half2_rn(acc.z, acc.w);
        uint32_t off = (uint32_t)(local * 128 + ((c16 ^ (local & 7)) << 4) + h8);
        *(uint2*)(buf + chunk * 16384 + off) =
            make_uint2(*(uint32_t*)&h0, *(uint32_t*)&h1);
    }
}

__global__ __launch_bounds__(448, 1)
void fused_k(const float* __restrict__ bias1, const float* __restrict__ bias2,
             const int* __restrict__ mask, const float* __restrict__ emb32,
             float* __restrict__ outp) {
    extern __shared__ __align__(128) char smem[];
    int tid  = threadIdx.x;
    int lane = tid & 31;
    int wid  = tid >> 5;
    uint32_t sb = smem_u32(smem);

    // ---- prologue: consumers load W1+W2 once; producers gather tile0 ----
    if (wid < 8) {
#pragma unroll
        for (int i = 0; i < 16; i++) {
            int idx = i * 256 + tid;
            int k = idx >> 4, c = idx & 15;
            uint32_t off = (uint32_t)(k * 256 + ((c ^ (k & 7)) << 4));
            *(uint4*)(smem + SM_W1 + off) =
                *(const uint4*)(g_w1_16 + (size_t)k * 128 + c * 8);
        }
#pragma unroll
        for (int i = 0; i < 8; i++) {
            int idx = i * 256 + tid;
            int k = idx >> 4, c = idx & 15;
            uint32_t off = (uint32_t)(k * 256 + ((c ^ (k & 7)) << 4));
            *(uint4*)(smem + SM_W2 + off) =
                *(const uint4*)(g_w2_16 + (size_t)k * 128 + c * 8);
        }
    } else {
        produce(smem + SM_BUF, blockIdx.x * 128, tid - 256, lane, wid - 8);
    }
    __syncthreads();

    int wm = wid & 3, wn = (wid >> 2) & 1;
    int g = lane >> 2, tig = lane & 3;
    float acc[2][8][4];

    int it = 0;
    for (int tile = blockIdx.x; tile < NTILES; tile += gridDim.x, ++it) {
        char* buf = smem + SM_BUF + (it & 1) * 65536;

        if (wid < 8) {
            // ================= consumers =================
            uint32_t bufu = sb + SM_BUF + (uint32_t)((it & 1) * 65536);
            int rowBase = tile * 128;

            auto mma_block = [&](uint32_t aB, uint32_t bB, int kk, int kAbs) {
                uint32_t aF[2][4], bF[4][4];
#pragma unroll
                for (int mi = 0; mi < 2; mi++) {
                    int r = wm * 32 + mi * 16 + (lane & 15);
                    int c = kk * 2 + (lane >> 4);
                    uint32_t off = (uint32_t)(r * 128 + ((c ^ (r & 7)) << 4));
                    ldsm4(aF[mi], aB + off);
                }
#pragma unroll
                for (int q = 0; q < 4; q++) {
                    int k = kAbs + (lane & 15);
                    int c = (wn * 64 + q * 16 + ((lane >> 4) << 3)) >> 3;
                    uint32_t boff = (uint32_t)(k * 256 + ((c ^ (k & 7)) << 4));
                    ldsm4t(bF[q], bB + boff);
                }
#pragma unroll
                for (int mi = 0; mi < 2; mi++)
#pragma unroll
                    for (int n8 = 0; n8 < 8; n8++)
                        mma16816(acc[mi][n8], aF[mi],
                                 bF[n8 >> 1][(n8 & 1) * 2],
                                 bF[n8 >> 1][(n8 & 1) * 2 + 1]);
            };

            // ---- GEMM1: K=256, all 4 chunks resident ----
#pragma unroll
            for (int mi = 0; mi < 2; mi++)
#pragma unroll
                for (int n8 = 0; n8 < 8; n8++)
#pragma unroll
                    for (int q = 0; q < 4; q++) acc[mi][n8][q] = 0.f;
#pragma unroll
            for (int ch = 0; ch < 4; ch++)
#pragma unroll
                for (int kk = 0; kk < 4; kk++)
                    mma_block(bufu + ch * 16384, sb + SM_W1, kk, ch * 64 + kk * 16);

            bar_consumers();   // all consumer reads of chunks 0-1 done

            // ---- epilogue1: relu+bias -> h fp16 into chunks 0-1 ----
#pragma unroll
            for (int mi = 0; mi < 2; mi++) {
#pragma unroll
                for (int half = 0; half < 2; half++) {
                    int rl = wm * 32 + mi * 16 + g + half * 8;
#pragma unroll
                    for (int n8 = 0; n8 < 8; n8++) {
                        int cidx = wn * 64 + n8 * 8 + tig * 2;
                        float x0 = fmaxf(acc[mi][n8][half * 2 + 0] + __ldg(bias1 + cidx), 0.f);
                        float x1 = fmaxf(acc[mi][n8][half * 2 + 1] + __ldg(bias1 + cidx + 1), 0.f);
                        __half2 hv = __floats2half2_rn(x0, x1);
                        uint32_t off = (uint32_t)(rl * 128 + ((n8 ^ (rl & 7)) << 4) + tig * 4);
                        *(uint32_t*)(buf + wn * 16384 + off) = *(uint32_t*)&hv;
                    }
                }
            }
            bar_consumers();   // h visible

            // ---- GEMM2: K=128, A = h chunks 0-1 ----
#pragma unroll
            for (int mi = 0; mi < 2; mi++)
#pragma unroll
                for (int n8 = 0; n8 < 8; n8++)
#pragma unroll
                    for (int q = 0; q < 4; q++) acc[mi][n8][q] = 0.f;
#pragma unroll
            for (int ch = 0; ch < 2; ch++)
#pragma unroll
                for (int kk = 0; kk < 4; kk++)
                    mma_block(bufu + ch * 16384, sb + SM_W2, kk, ch * 64 + kk * 16);

            // ---- epilogue2: bias + mask select -> out ----
#pragma unroll
            for (int mi = 0; mi < 2; mi++) {
#pragma unroll
                for (int half = 0; half < 2; half++) {
                    int r = rowBase + wm * 32 + mi * 16 + g + half * 8;
                    bool doImp = (mask[r] != 0);
#pragma unroll
                    for (int n8 = 0; n8 < 8; n8++) {
                        int cidx = wn * 64 + n8 * 8 + tig * 2;
                        float2 v;
                        v.x = acc[mi][n8][half * 2 + 0] + __ldg(bias2 + cidx);
                        v.y = acc[mi][n8][half * 2 + 1] + __ldg(bias2 + cidx + 1);
                        if (!doImp)
                            v = *(const float2*)(emb32 + (size_t)r * 128 + cidx);
                        *(float2*)(outp + (size_t)r * 128 + cidx) = v;
                    }
                }
            }
        } else {
            // ================= producers: build next tile's ctx =================
            int nt = tile + gridDim.x;
            if (nt < NTILES)
                produce(smem + SM_BUF + (uint32_t)(((it & 1) ^ 1) * 65536),
                        nt * 128, tid - 256, lane, wid - 8);
        }
        __syncthreads();
    }
}

// ---------------- launch -------------------------------------------------------
extern "C" void kernel_launch(void* const* d_in, const int* in_sizes, int n_in,
                              void* d_out, int out_size) {
    const float* emb  = (const float*)d_in[0];
    const int*   mask = (const int*)d_in[1];
    const int*   edge = (const int*)d_in[2];
    const float* W1   = (const float*)d_in[3];
    const float* b1   = (const float*)d_in[4];
    const float* W2   = (const float*)d_in[5];
    const float* b2   = (const float*)d_in[6];
    float*       out  = (float*)d_out;

    cudaFuncSetAttribute(fused_k,
                         cudaFuncAttributeMaxDynamicSharedMemorySize, SMEM_FUSED);
    int dev = 0, sms = 148;
    cudaGetDevice(&dev);
    cudaDeviceGetAttribute(&sms, cudaDevAttrMultiProcessorCount, dev);
    if (sms > NTILES) sms = NTILES;

    // emb fp16 copy (+ zero counts), then CSR build
    econv16_k<<<NROWS * HDIM / (256 * 8), 256>>>(emb);
    hist_k<<<(NEDGES + 255) / 256, 256>>>(edge);
    scan_k<<<1, 1024>>>();
    scatter_k<<<(NEDGES + 255) / 256, 256>>>(edge);

    // weight converts (tiny)
    __half *w1p, *w2p;
    cudaGetSymbolAddress((void**)&w1p, g_w1_16);
    cudaGetSymbolAddress((void**)&w2p, g_w2_16);
    wconv_k<<<128, 256>>>(W1, w1p, 256 * 128);
    wconv_k<<<64, 256>>>(W2, w2p, 128 * 128);

    // fused gather + GEMM1 + GEMM2 (warp-specialized, persistent)
    fused_k<<<sms, 448, SMEM_FUSED>>>(b1, b2, mask, emb, out);
}